// round 11
// baseline (speedup 1.0000x reference)
#include <cuda_runtime.h>
#include <cuda_fp16.h>

#define Bn 8
#define Hn 192
#define Wn 192
#define Sn 4
#define Cn 32

// Two ping-pong scratch arrays sized for the largest scale (w=18), shared by
// all scales (sequential execution). Live set <= 45+53 = 98 MB < 126 MB L2.
__device__ __half2 g_1[11206656 + 262144];   // s1/s3 out: (Hn+2w)*Wn / Hn*(Wn+2w)
__device__ __half2 g_2[13307904 + 262144];   // s2 out: (Hn+2w)*(Wn+2w)

template<int WID> struct SP;
template<> struct SP<1>  { static constexpr int SI = 0; static constexpr float INVS2 = 16.0f; };
template<> struct SP<3>  { static constexpr int SI = 1; static constexpr float INVS2 = 1.77777778f; };
template<> struct SP<8>  { static constexpr int SI = 2; static constexpr float INVS2 = 0.326530612f; };
template<> struct SP<18> { static constexpr int SI = 3; static constexpr float INVS2 = 0.0711111111f; };

// exact fp16 bit pattern for small non-negative integers (n <= 2048), duplicated.
struct TapArr { unsigned int v[64]; };
template<int L, int WID>
__host__ __device__ constexpr TapArr mk_taps() {
    TapArr t{};
    for (int j = 0; j < L; ++j) {
        int n = (j - WID) * (j - WID);
        unsigned short h = 0;
        if (n > 0) {
            int hb = 0;
            for (int i = 0; i < 12; ++i) if ((n >> i) & 1) hb = i;
            unsigned short mant = (unsigned short)((((unsigned)(n - (1 << hb))) << 10) >> hb);
            h = (unsigned short)(((15 + hb) << 10) | mant);
        }
        t.v[j] = (unsigned)h | ((unsigned)h << 16);
    }
    return t;
}

// All stages run max-chains on packed half2:
//  s1: in x fp32 -> u=(v,-v);  acc=(vc1, -vo1)           taps -a
//  s2: in (vc1,-vo1) direct;   acc=(vc2, -vo2)           taps -a
//  s3: in (vc2,-vo2), u=-in;   acc=(-vc3, vo3)           taps -a*c
//  s4: in (-vc3,vo3) direct;   acc=(-vc4, vo4) -> blend  taps -a*c
template<int WID, int STAGE, int BH>
__global__ __launch_bounds__(128)
void morph(const __half2* __restrict__ in, __half2* __restrict__ out,
           const float* __restrict__ x,
           const float* __restrict__ coef, const float* __restrict__ cmul,
           const float* __restrict__ alpha, float* __restrict__ outF)
{
    constexpr int  L = 2 * WID + 1;
    constexpr int  P = 2 * WID;
    constexpr int  M = BH + L - 1;     // inputs per block along morph axis
    constexpr int  CH = 16;            // prefetch chunk
    constexpr int NM = (STAGE == 1) ? (Hn + P) : (STAGE == 2) ? (Wn + P)
                     : (STAGE == 3) ? Hn : Wn;
    constexpr int NL = (STAGE == 1) ? Wn : (STAGE == 2) ? (Hn + P)
                     : (STAGE == 3) ? (Wn + P) : Hn;
    constexpr TapArr TT = mk_taps<L, WID>();

    const int lane = threadIdx.x & 31;
    const int warp = threadIdx.x >> 5;
    const int b    = blockIdx.z;
    const int line = blockIdx.y * 4 + warp;
    const int a0   = blockIdx.x * BH;
    if (line >= NL) return;

    float af = coef[lane] * SP<WID>::INVS2;
    if (STAGE >= 3) af *= cmul[lane];
    const __half2 ah2 = __float2half2_rn(-af);

    const __half2 NINF = __halves2half2(__ushort_as_half(0xFC00), __ushort_as_half(0xFC00));
    __half2 acc[BH];
#pragma unroll
    for (int p = 0; p < BH; ++p) acc[p] = NINF;

    auto tap = [&](__half2 u, int m) {
#pragma unroll
        for (int p = 0; p < BH; ++p) {
            int j = m - p;
            if (j < 0 || j >= L) continue;
            unsigned int tb = TT.v[j];
            __half2 dj = *reinterpret_cast<const __half2*>(&tb);
            acc[p] = __hmax2(acc[p], __hfma2(dj, ah2, u));
        }
    };

    if constexpr (STAGE == 1) {
        const float* px = x + ((b * Hn * Wn + line) * Sn + SP<WID>::SI) * Cn + lane;
        constexpr int RS = Wn * Sn * Cn;
        const bool interior = (a0 >= P) && (a0 + M - 1 - P <= Hn - 1);
        if (interior) {
            const float* p0 = px + (a0 - P) * RS;
#pragma unroll
            for (int m0 = 0; m0 < M; m0 += CH) {
                float u[CH];
#pragma unroll
                for (int q = 0; q < CH; ++q)
                    if (m0 + q < M) u[q] = __ldg(p0 + (m0 + q) * RS);
#pragma unroll
                for (int q = 0; q < CH; ++q)
                    if (m0 + q < M) tap(__floats2half2_rn(u[q], -u[q]), m0 + q);
            }
        } else {
#pragma unroll
            for (int m0 = 0; m0 < M; m0 += CH) {
                float u[CH];
#pragma unroll
                for (int q = 0; q < CH; ++q)
                    if (m0 + q < M) {
                        int xh = min(max(a0 + m0 + q - P, 0), Hn - 1);
                        u[q] = __ldg(px + xh * RS);
                    }
#pragma unroll
                for (int q = 0; q < CH; ++q)
                    if (m0 + q < M) tap(__floats2half2_rn(u[q], -u[q]), m0 + q);
            }
        }
    } else if constexpr (STAGE == 2) {
        const __half2* pr = in + (b * (Hn + P) + line) * (Wn * Cn) + lane;
        const bool interior = (a0 >= P) && (a0 + M - 1 - P <= Wn - 1);
        if (interior) {
            const __half2* p0 = pr + (a0 - P) * Cn;
#pragma unroll
            for (int m0 = 0; m0 < M; m0 += CH) {
                __half2 u[CH];
#pragma unroll
                for (int q = 0; q < CH; ++q)
                    if (m0 + q < M) u[q] = __ldg(p0 + (m0 + q) * Cn);
#pragma unroll
                for (int q = 0; q < CH; ++q)
                    if (m0 + q < M) tap(u[q], m0 + q);
            }
        } else {
#pragma unroll
            for (int m0 = 0; m0 < M; m0 += CH) {
                __half2 u[CH];
#pragma unroll
                for (int q = 0; q < CH; ++q)
                    if (m0 + q < M) {
                        int cidx = min(max(a0 + m0 + q - P, 0), Wn - 1);
                        u[q] = __ldg(pr + cidx * Cn);
                    }
#pragma unroll
                for (int q = 0; q < CH; ++q)
                    if (m0 + q < M) tap(u[q], m0 + q);
            }
        }
    } else if constexpr (STAGE == 3) {
        const __half2* p0 = in + ((b * (Hn + P) + a0) * (Wn + P) + line) * Cn + lane;
        constexpr int MS = (Wn + P) * Cn;
#pragma unroll
        for (int m0 = 0; m0 < M; m0 += CH) {
            __half2 u[CH];
#pragma unroll
            for (int q = 0; q < CH; ++q)
                if (m0 + q < M) u[q] = __ldg(p0 + (m0 + q) * MS);
#pragma unroll
            for (int q = 0; q < CH; ++q)
                if (m0 + q < M) tap(__hneg2(u[q]), m0 + q);
        }
    } else {
        const __half2* p0 = in + ((b * Hn + line) * (Wn + P) + a0) * Cn + lane;
#pragma unroll
        for (int m0 = 0; m0 < M; m0 += CH) {
            __half2 u[CH];
#pragma unroll
            for (int q = 0; q < CH; ++q)
                if (m0 + q < M) u[q] = __ldg(p0 + (m0 + q) * Cn);
#pragma unroll
            for (int q = 0; q < CH; ++q)
                if (m0 + q < M) tap(u[q], m0 + q);
        }
    }

    if constexpr (STAGE == 4) {
        float al = alpha[lane];
#pragma unroll
        for (int p = 0; p < BH; ++p) {
            float vc = -__low2float(acc[p]);
            float vo =  __high2float(acc[p]);
            float r  = fmaf(al, vc - vo, vo);   // alpha*xc + (1-alpha)*xo
            outF[(((b * Hn + line) * Wn + (a0 + p)) * Sn + SP<WID>::SI) * Cn + lane] = r;
        }
    } else if constexpr (STAGE == 1) {   // rows Hn+P x cols Wn — GUARDED
        const int base = ((b * (Hn + P) + a0) * Wn + line) * Cn + lane;
#pragma unroll
        for (int p = 0; p < BH; ++p) {
            if (a0 + p >= NM) continue;
            out[base + p * (Wn * Cn)] = acc[p];
        }
    } else if constexpr (STAGE == 2) {   // rows Hn+P x cols Wn+P — GUARDED
        const int base = ((b * (Hn + P) + line) * (Wn + P) + a0) * Cn + lane;
#pragma unroll
        for (int p = 0; p < BH; ++p) {
            if (a0 + p >= NM) continue;
            out[base + p * Cn] = acc[p];
        }
    } else {                              // stage 3: rows Hn (exact tiles)
        const int base = ((b * Hn + a0) * (Wn + P) + line) * Cn + lane;
#pragma unroll
        for (int p = 0; p < BH; ++p) out[base + p * ((Wn + P) * Cn)] = acc[p];
    }
}

static inline int cdiv(int a, int b) { return (a + b - 1) / b; }

template<int WID>
static void run_scale(const float* x, const float* coef, const float* cm,
                      const float* al, float* out, __half2* g1, __half2* g2)
{
    constexpr int BH = 16;
    constexpr int P = 2 * WID;
    morph<WID, 1, BH><<<dim3(cdiv(Hn + P, BH), cdiv(Wn, 4),     Bn), 128>>>(
        nullptr, g1, x, coef, cm, al, nullptr);
    morph<WID, 2, BH><<<dim3(cdiv(Wn + P, BH), cdiv(Hn + P, 4), Bn), 128>>>(
        g1, g2, nullptr, coef, cm, al, nullptr);
    morph<WID, 3, BH><<<dim3(cdiv(Hn, BH),     cdiv(Wn + P, 4), Bn), 128>>>(
        g2, g1, nullptr, coef, cm, al, nullptr);
    morph<WID, 4, BH><<<dim3(cdiv(Wn, BH),     cdiv(Hn, 4),     Bn), 128>>>(
        g1, nullptr, nullptr, coef, cm, al, out);
}

extern "C" void kernel_launch(void* const* d_in, const int* in_sizes, int n_in,
                              void* d_out, int out_size)
{
    const float* x    = (const float*)d_in[0];
    const float* coef = (const float*)d_in[1];
    const float* cm   = (const float*)d_in[2];
    const float* al   = (const float*)d_in[3];
    float* out = (float*)d_out;

    __half2 *g1, *g2;
    cudaGetSymbolAddress((void**)&g1, g_1);
    cudaGetSymbolAddress((void**)&g2, g_2);

    // Sequential scales, full batch: one scale's scratch (<=98 MB) stays
    // L2-resident; full-size grids (>=2.5 waves) amortize tails.
    run_scale<18>(x, coef, cm, al, out, g1, g2);
    run_scale<8> (x, coef, cm, al, out, g1, g2);
    run_scale<3> (x, coef, cm, al, out, g1, g2);
    run_scale<1> (x, coef, cm, al, out, g1, g2);
}

// round 12
// speedup vs baseline: 1.1179x; 1.1179x over previous
#include <cuda_runtime.h>
#include <cuda_fp16.h>

#define Bn 8
#define Hn 192
#define Wn 192
#define Sn 4
#define Cn 32

// Private scratch per scale (all 4 scales run concurrently, one stream each).
__device__ __half2 gA1[11206656 + 65536];  // w18: 228*192*256
__device__ __half2 gA2[13307904 + 65536];  // w18: 228*228*256
__device__ __half2 gB1[10223616 + 65536];  // w8:  208*192*256
__device__ __half2 gB2[11075584 + 65536];  // w8:  208*208*256
__device__ __half2 gC1[ 9732096 + 65536];  // w3:  198*192*256
__device__ __half2 gC2[10036224 + 65536];  // w3:  198*198*256
__device__ __half2 gD1[ 9535488 + 65536];  // w1:  194*192*256
__device__ __half2 gD2[ 9634816 + 65536];  // w1:  194*194*256

template<int WID> struct SP;
template<> struct SP<1>  { static constexpr int SI = 0; static constexpr float INVS2 = 16.0f; };
template<> struct SP<3>  { static constexpr int SI = 1; static constexpr float INVS2 = 1.77777778f; };
template<> struct SP<8>  { static constexpr int SI = 2; static constexpr float INVS2 = 0.326530612f; };
template<> struct SP<18> { static constexpr int SI = 3; static constexpr float INVS2 = 0.0711111111f; };

// exact fp16 bit pattern for small non-negative integers (n <= 2048), duplicated.
struct TapArr { unsigned int v[64]; };
template<int L, int WID>
__host__ __device__ constexpr TapArr mk_taps() {
    TapArr t{};
    for (int j = 0; j < L; ++j) {
        int n = (j - WID) * (j - WID);
        unsigned short h = 0;
        if (n > 0) {
            int hb = 0;
            for (int i = 0; i < 12; ++i) if ((n >> i) & 1) hb = i;
            unsigned short mant = (unsigned short)((((unsigned)(n - (1 << hb))) << 10) >> hb);
            h = (unsigned short)(((15 + hb) << 10) | mant);
        }
        t.v[j] = (unsigned)h | ((unsigned)h << 16);
    }
    return t;
}

// All stages run max-chains on packed half2:
//  s1: in x fp32 -> u=(v,-v);  acc=(vc1, -vo1)           taps -a
//  s2: in (vc1,-vo1) direct;   acc=(vc2, -vo2)           taps -a
//  s3: in (vc2,-vo2), u=-in;   acc=(-vc3, vo3)           taps -a*c
//  s4: in (-vc3,vo3) direct;   acc=(-vc4, vo4) -> blend  taps -a*c
template<int WID, int STAGE, int BH>
__global__ __launch_bounds__(128)
void morph(const __half2* __restrict__ in, __half2* __restrict__ out,
           const float* __restrict__ x,
           const float* __restrict__ coef, const float* __restrict__ cmul,
           const float* __restrict__ alpha, float* __restrict__ outF)
{
    constexpr int  L = 2 * WID + 1;
    constexpr int  P = 2 * WID;
    constexpr int  M = BH + L - 1;     // inputs per block along morph axis
    constexpr int  CH = 16;            // prefetch chunk
    constexpr int NM = (STAGE == 1) ? (Hn + P) : (STAGE == 2) ? (Wn + P)
                     : (STAGE == 3) ? Hn : Wn;
    constexpr int NL = (STAGE == 1) ? Wn : (STAGE == 2) ? (Hn + P)
                     : (STAGE == 3) ? (Wn + P) : Hn;
    constexpr TapArr TT = mk_taps<L, WID>();

    const int lane = threadIdx.x & 31;
    const int warp = threadIdx.x >> 5;
    const int b    = blockIdx.z;
    const int line = blockIdx.y * 4 + warp;
    const int a0   = blockIdx.x * BH;
    if (line >= NL) return;

    float af = coef[lane] * SP<WID>::INVS2;
    if (STAGE >= 3) af *= cmul[lane];
    const __half2 ah2 = __float2half2_rn(-af);

    const __half2 NINF = __halves2half2(__ushort_as_half(0xFC00), __ushort_as_half(0xFC00));
    __half2 acc[BH];
#pragma unroll
    for (int p = 0; p < BH; ++p) acc[p] = NINF;

    auto tap = [&](__half2 u, int m) {
#pragma unroll
        for (int p = 0; p < BH; ++p) {
            int j = m - p;
            if (j < 0 || j >= L) continue;
            unsigned int tb = TT.v[j];
            __half2 dj = *reinterpret_cast<const __half2*>(&tb);
            acc[p] = __hmax2(acc[p], __hfma2(dj, ah2, u));
        }
    };

    if constexpr (STAGE == 1) {
        const float* px = x + ((b * Hn * Wn + line) * Sn + SP<WID>::SI) * Cn + lane;
        constexpr int RS = Wn * Sn * Cn;
        const bool interior = (a0 >= P) && (a0 + M - 1 - P <= Hn - 1);
        if (interior) {
            const float* p0 = px + (a0 - P) * RS;
#pragma unroll
            for (int m0 = 0; m0 < M; m0 += CH) {
                float u[CH];
#pragma unroll
                for (int q = 0; q < CH; ++q)
                    if (m0 + q < M) u[q] = __ldg(p0 + (m0 + q) * RS);
#pragma unroll
                for (int q = 0; q < CH; ++q)
                    if (m0 + q < M) tap(__floats2half2_rn(u[q], -u[q]), m0 + q);
            }
        } else {
#pragma unroll
            for (int m0 = 0; m0 < M; m0 += CH) {
                float u[CH];
#pragma unroll
                for (int q = 0; q < CH; ++q)
                    if (m0 + q < M) {
                        int xh = min(max(a0 + m0 + q - P, 0), Hn - 1);
                        u[q] = __ldg(px + xh * RS);
                    }
#pragma unroll
                for (int q = 0; q < CH; ++q)
                    if (m0 + q < M) tap(__floats2half2_rn(u[q], -u[q]), m0 + q);
            }
        }
    } else if constexpr (STAGE == 2) {
        const __half2* pr = in + (b * (Hn + P) + line) * (Wn * Cn) + lane;
        const bool interior = (a0 >= P) && (a0 + M - 1 - P <= Wn - 1);
        if (interior) {
            const __half2* p0 = pr + (a0 - P) * Cn;
#pragma unroll
            for (int m0 = 0; m0 < M; m0 += CH) {
                __half2 u[CH];
#pragma unroll
                for (int q = 0; q < CH; ++q)
                    if (m0 + q < M) u[q] = __ldg(p0 + (m0 + q) * Cn);
#pragma unroll
                for (int q = 0; q < CH; ++q)
                    if (m0 + q < M) tap(u[q], m0 + q);
            }
        } else {
#pragma unroll
            for (int m0 = 0; m0 < M; m0 += CH) {
                __half2 u[CH];
#pragma unroll
                for (int q = 0; q < CH; ++q)
                    if (m0 + q < M) {
                        int cidx = min(max(a0 + m0 + q - P, 0), Wn - 1);
                        u[q] = __ldg(pr + cidx * Cn);
                    }
#pragma unroll
                for (int q = 0; q < CH; ++q)
                    if (m0 + q < M) tap(u[q], m0 + q);
            }
        }
    } else if constexpr (STAGE == 3) {
        const __half2* p0 = in + ((b * (Hn + P) + a0) * (Wn + P) + line) * Cn + lane;
        constexpr int MS = (Wn + P) * Cn;
#pragma unroll
        for (int m0 = 0; m0 < M; m0 += CH) {
            __half2 u[CH];
#pragma unroll
            for (int q = 0; q < CH; ++q)
                if (m0 + q < M) u[q] = __ldg(p0 + (m0 + q) * MS);
#pragma unroll
            for (int q = 0; q < CH; ++q)
                if (m0 + q < M) tap(__hneg2(u[q]), m0 + q);
        }
    } else {
        const __half2* p0 = in + ((b * Hn + line) * (Wn + P) + a0) * Cn + lane;
#pragma unroll
        for (int m0 = 0; m0 < M; m0 += CH) {
            __half2 u[CH];
#pragma unroll
            for (int q = 0; q < CH; ++q)
                if (m0 + q < M) u[q] = __ldg(p0 + (m0 + q) * Cn);
#pragma unroll
            for (int q = 0; q < CH; ++q)
                if (m0 + q < M) tap(u[q], m0 + q);
        }
    }

    if constexpr (STAGE == 4) {
        float al = alpha[lane];
#pragma unroll
        for (int p = 0; p < BH; ++p) {
            float vc = -__low2float(acc[p]);
            float vo =  __high2float(acc[p]);
            float r  = fmaf(al, vc - vo, vo);   // alpha*xc + (1-alpha)*xo
            outF[(((b * Hn + line) * Wn + (a0 + p)) * Sn + SP<WID>::SI) * Cn + lane] = r;
        }
    } else if constexpr (STAGE == 1) {   // rows Hn+P x cols Wn — GUARDED
        const int base = ((b * (Hn + P) + a0) * Wn + line) * Cn + lane;
#pragma unroll
        for (int p = 0; p < BH; ++p) {
            if (a0 + p >= NM) continue;
            out[base + p * (Wn * Cn)] = acc[p];
        }
    } else if constexpr (STAGE == 2) {   // rows Hn+P x cols Wn+P — GUARDED
        const int base = ((b * (Hn + P) + line) * (Wn + P) + a0) * Cn + lane;
#pragma unroll
        for (int p = 0; p < BH; ++p) {
            if (a0 + p >= NM) continue;
            out[base + p * Cn] = acc[p];
        }
    } else {                              // stage 3: rows Hn (exact tiles)
        const int base = ((b * Hn + a0) * (Wn + P) + line) * Cn + lane;
#pragma unroll
        for (int p = 0; p < BH; ++p) out[base + p * ((Wn + P) * Cn)] = acc[p];
    }
}

static inline int cdiv(int a, int b) { return (a + b - 1) / b; }

template<int WID>
static void run_scale(const float* x, const float* coef, const float* cm,
                      const float* al, float* out, __half2* g1, __half2* g2,
                      cudaStream_t st)
{
    constexpr int BH = 16;
    constexpr int P = 2 * WID;
    morph<WID, 1, BH><<<dim3(cdiv(Hn + P, BH), cdiv(Wn, 4),     Bn), 128, 0, st>>>(
        nullptr, g1, x, coef, cm, al, nullptr);
    morph<WID, 2, BH><<<dim3(cdiv(Wn + P, BH), cdiv(Hn + P, 4), Bn), 128, 0, st>>>(
        g1, g2, nullptr, coef, cm, al, nullptr);
    morph<WID, 3, BH><<<dim3(cdiv(Hn, BH),     cdiv(Wn + P, 4), Bn), 128, 0, st>>>(
        g2, g1, nullptr, coef, cm, al, nullptr);
    morph<WID, 4, BH><<<dim3(cdiv(Wn, BH),     cdiv(Hn, 4),     Bn), 128, 0, st>>>(
        g1, nullptr, nullptr, coef, cm, al, out);
}

extern "C" void kernel_launch(void* const* d_in, const int* in_sizes, int n_in,
                              void* d_out, int out_size)
{
    const float* x    = (const float*)d_in[0];
    const float* coef = (const float*)d_in[1];
    const float* cm   = (const float*)d_in[2];
    const float* al   = (const float*)d_in[3];
    float* out = (float*)d_out;

    __half2 *a1, *a2, *b1, *b2, *c1, *c2, *d1, *d2;
    cudaGetSymbolAddress((void**)&a1, gA1);
    cudaGetSymbolAddress((void**)&a2, gA2);
    cudaGetSymbolAddress((void**)&b1, gB1);
    cudaGetSymbolAddress((void**)&b2, gB2);
    cudaGetSymbolAddress((void**)&c1, gC1);
    cudaGetSymbolAddress((void**)&c2, gC2);
    cudaGetSymbolAddress((void**)&d1, gD1);
    cudaGetSymbolAddress((void**)&d2, gD2);

    static cudaStream_t s1 = nullptr, s2 = nullptr, s3 = nullptr;
    static cudaEvent_t evF = nullptr, ev1 = nullptr, ev2 = nullptr, ev3 = nullptr;
    if (!s1) {
        cudaStreamCreateWithFlags(&s1, cudaStreamNonBlocking);
        cudaStreamCreateWithFlags(&s2, cudaStreamNonBlocking);
        cudaStreamCreateWithFlags(&s3, cudaStreamNonBlocking);
        cudaEventCreateWithFlags(&evF, cudaEventDisableTiming);
        cudaEventCreateWithFlags(&ev1, cudaEventDisableTiming);
        cudaEventCreateWithFlags(&ev2, cudaEventDisableTiming);
        cudaEventCreateWithFlags(&ev3, cudaEventDisableTiming);
    }

    // Fork: one stream per scale, all four scales fully concurrent.
    cudaEventRecord(evF, 0);
    cudaStreamWaitEvent(s1, evF, 0);
    cudaStreamWaitEvent(s2, evF, 0);
    cudaStreamWaitEvent(s3, evF, 0);

    run_scale<18>(x, coef, cm, al, out, a1, a2, (cudaStream_t)0);
    run_scale<8> (x, coef, cm, al, out, b1, b2, s1);
    run_scale<3> (x, coef, cm, al, out, c1, c2, s2);
    run_scale<1> (x, coef, cm, al, out, d1, d2, s3);

    // Join
    cudaEventRecord(ev1, s1); cudaStreamWaitEvent((cudaStream_t)0, ev1, 0);
    cudaEventRecord(ev2, s2); cudaStreamWaitEvent((cudaStream_t)0, ev2, 0);
    cudaEventRecord(ev3, s3); cudaStreamWaitEvent((cudaStream_t)0, ev3, 0);
}